// round 8
// baseline (speedup 1.0000x reference)
#include <cuda_runtime.h>
#include <cuda_fp16.h>

#define N_NODES 100000
#define N_EDGES 1250000
#define F 64
#define NBLK 391        // ceil(N_NODES/256)

// Scratch (device globals — no allocation allowed in kernel_launch)
__device__ int   g_deg[N_NODES];
__device__ float g_dinv[N_NODES];
__device__ int   g_row_start[N_NODES + 1];
__device__ int   g_cursor[N_NODES];
__device__ unsigned long long g_bsv[512];            // flagged block sums
__device__ int   g_ssrc[N_EDGES];                    // src ids sorted by dst
__device__ __align__(16) __half g_hs[N_NODES * F];   // fp16 h (UNSCALED)

__global__ void k_zero() {
    int i = blockIdx.x * blockDim.x + threadIdx.x;
    if (i < N_NODES) g_deg[i] = 0;
    if (i < 512) g_bsv[i] = 0ULL;
}

__global__ void k_count(const int* __restrict__ ei) {
    int e = blockIdx.x * blockDim.x + threadIdx.x;
    if (e < N_EDGES) atomicAdd(&g_deg[ei[N_EDGES + e]], 1);
}

// Single-pass exclusive scan over g_deg (publish block total, poll predecessors)
// + dinv + cursor init, all fused.
__global__ void k_scanF() {
    __shared__ int sd[256];
    const int tid = threadIdx.x, bid = blockIdx.x;
    const int i = bid * 256 + tid;
    int v = (i < N_NODES) ? g_deg[i] : 0;
    sd[tid] = v;
    __syncthreads();
    #pragma unroll
    for (int off = 1; off < 256; off <<= 1) {
        int t = (tid >= off) ? sd[tid - off] : 0;
        __syncthreads();
        sd[tid] += t;
        __syncthreads();
    }
    int incl = sd[tid];
    // publish own block total BEFORE polling predecessors (no circular wait)
    if (tid == 255)
        atomicExch(&g_bsv[bid], (1ULL << 63) | (unsigned long long)(unsigned)incl);

    // poll predecessors: thread t handles p = t, t+256 (< bid)
    int s = 0;
    for (int p = tid; p < bid; p += 256) {
        unsigned long long x;
        do { x = atomicAdd(&g_bsv[p], 0ULL); } while (!(x >> 63));
        s += (int)(unsigned)x;
    }
    __syncthreads();
    sd[tid] = s;
    __syncthreads();
    #pragma unroll
    for (int off = 128; off > 0; off >>= 1) {
        if (tid < off) sd[tid] += sd[tid + off];
        __syncthreads();
    }
    int boff = sd[0];

    if (i < N_NODES) {
        int rs = incl - v + boff;            // exclusive global offset
        g_row_start[i] = rs;
        g_cursor[i] = rs;
        g_dinv[i] = rsqrtf((float)v + 1.0f); // +1 self-loop
    }
    if (i == 0) g_row_start[N_NODES] = N_EDGES;
}

__global__ void k_place(const int* __restrict__ ei) {
    int e = blockIdx.x * blockDim.x + threadIdx.x;
    if (e < N_EDGES) {
        int d = ei[N_EDGES + e];
        int pos = atomicAdd(&g_cursor[d], 1);
        g_ssrc[pos] = ei[e];
    }
}

// ---- tensor-core GEMM: hs[n][j] = x[n] . W[j], fp16 out (NO dinv dep) ----
__device__ __forceinline__ unsigned pack_h2(float lo, float hi) {
    __half2 h = __floats2half2_rn(lo, hi);   // lo -> low half
    return *reinterpret_cast<unsigned*>(&h);
}

__device__ __forceinline__ void mma16816(float* c,
    unsigned a0, unsigned a1, unsigned a2, unsigned a3,
    unsigned b0, unsigned b1)
{
    asm volatile(
        "mma.sync.aligned.m16n8k16.row.col.f32.f16.f16.f32 "
        "{%0,%1,%2,%3}, {%4,%5,%6,%7}, {%8,%9}, {%0,%1,%2,%3};"
        : "+f"(c[0]), "+f"(c[1]), "+f"(c[2]), "+f"(c[3])
        : "r"(a0), "r"(a1), "r"(a2), "r"(a3), "r"(b0), "r"(b1));
}

#define WH_STRIDE 72   // halves per row (64 + 8 pad) -> conflict-free LDS.32
__global__ void __launch_bounds__(128) k_gemm(
    const float* __restrict__ x, const float* __restrict__ w)
{
    __shared__ __half Wh[64 * WH_STRIDE];   // [j][k] halves
    const int tid = threadIdx.x;

    {   // Stage W as fp16: 2048 float2 by 128 threads
        const float2* w2 = (const float2*)w;
        #pragma unroll
        for (int r = 0; r < 16; r++) {
            int idx = tid + 128 * r;       // float2 index 0..2047
            int j  = idx >> 5;             // 32 float2 per W row
            int kp = idx & 31;
            float2 v = w2[idx];
            *reinterpret_cast<unsigned*>(&Wh[j * WH_STRIDE + kp * 2]) = pack_h2(v.x, v.y);
        }
    }
    __syncthreads();

    const int warp = tid >> 5, lane = tid & 31;
    const int g = lane >> 2, t = lane & 3;
    const int r0 = blockIdx.x * 64 + warp * 16 + g;   // A rows r0, r0+8
    const int r1 = r0 + 8;
    const bool v0 = r0 < N_NODES, v1 = r1 < N_NODES;
    const float* xr0 = x + (size_t)r0 * F;
    const float* xr1 = x + (size_t)r1 * F;

    float acc[8][4] = {};   // 8 n-tiles x (c0..c3)

    #pragma unroll
    for (int kc = 0; kc < 4; kc++) {
        const int k0 = kc * 16 + t * 2;
        float2 f;
        f = v0 ? *(const float2*)(xr0 + k0)     : make_float2(0.f, 0.f);
        unsigned a0 = pack_h2(f.x, f.y);
        f = v1 ? *(const float2*)(xr1 + k0)     : make_float2(0.f, 0.f);
        unsigned a1 = pack_h2(f.x, f.y);
        f = v0 ? *(const float2*)(xr0 + k0 + 8) : make_float2(0.f, 0.f);
        unsigned a2 = pack_h2(f.x, f.y);
        f = v1 ? *(const float2*)(xr1 + k0 + 8) : make_float2(0.f, 0.f);
        unsigned a3 = pack_h2(f.x, f.y);

        const int kk = kc * 16 + t * 2;   // B k index
        #pragma unroll
        for (int nt = 0; nt < 8; nt++) {
            int n = nt * 8 + g;           // B col (output feature j)
            unsigned b0 = *reinterpret_cast<const unsigned*>(&Wh[n * WH_STRIDE + kk]);
            unsigned b1 = *reinterpret_cast<const unsigned*>(&Wh[n * WH_STRIDE + kk + 8]);
            mma16816(acc[nt], a0, a1, a2, a3, b0, b1);
        }
    }

    // Epilogue: store fp16 (unscaled)
    #pragma unroll
    for (int nt = 0; nt < 8; nt++) {
        int col = nt * 8 + t * 2;         // D cols col, col+1
        if (v0)
            *reinterpret_cast<unsigned*>(&g_hs[r0 * F + col]) =
                pack_h2(acc[nt][0], acc[nt][1]);
        if (v1)
            *reinterpret_cast<unsigned*>(&g_hs[r1 * F + col]) =
                pack_h2(acc[nt][2], acc[nt][3]);
    }
}

__device__ __forceinline__ void acc8s(float* a, uint4 v, float dv) {
    const __half2* h = reinterpret_cast<const __half2*>(&v);
    #pragma unroll
    for (int q = 0; q < 4; q++) {
        float2 f = __half22float2(h[q]);
        a[2 * q]     += f.x * dv;
        a[2 * q + 1] += f.y * dv;
    }
}

// CSR gather: 8 lanes per node; per edge: scalar dinv[src] + LDG.128 row.
// out[d] = bias + dinv[d] * ( dinv[d]*h[d] + sum_e dinv[s_e]*h[s_e] )
__global__ void __launch_bounds__(256) k_gather(
    const float* __restrict__ bias, float* __restrict__ out)
{
    long long tt = blockIdx.x * (long long)blockDim.x + threadIdx.x;
    int node = (int)(tt >> 3);
    int lane = threadIdx.x & 7;
    if (node >= N_NODES) return;

    const uint4* hs16 = (const uint4*)g_hs;   // 8 uint4 per row
    float dvn = __ldg(&g_dinv[node]);
    float a[8] = {0.f, 0.f, 0.f, 0.f, 0.f, 0.f, 0.f, 0.f};
    acc8s(a, hs16[node * 8 + lane], dvn);     // self-loop term

    int e   = __ldg(&g_row_start[node]);
    int end = __ldg(&g_row_start[node + 1]);

    for (; e + 2 <= end; e += 2) {
        int s0 = __ldg(&g_ssrc[e]);
        int s1 = __ldg(&g_ssrc[e + 1]);
        float d0 = __ldg(&g_dinv[s0]);
        float d1 = __ldg(&g_dinv[s1]);
        uint4 u0 = hs16[s0 * 8 + lane];
        uint4 u1 = hs16[s1 * 8 + lane];
        acc8s(a, u0, d0);
        acc8s(a, u1, d1);
    }
    if (e < end) {
        int s0 = __ldg(&g_ssrc[e]);
        float d0 = __ldg(&g_dinv[s0]);
        acc8s(a, hs16[s0 * 8 + lane], d0);
    }

    const float4* b4 = (const float4*)bias;
    float4 ba = b4[lane * 2], bb = b4[lane * 2 + 1];
    float4 o0, o1;
    o0.x = ba.x + dvn * a[0]; o0.y = ba.y + dvn * a[1];
    o0.z = ba.z + dvn * a[2]; o0.w = ba.w + dvn * a[3];
    o1.x = bb.x + dvn * a[4]; o1.y = bb.y + dvn * a[5];
    o1.z = bb.z + dvn * a[6]; o1.w = bb.w + dvn * a[7];
    ((float4*)out)[node * 16 + lane * 2]     = o0;
    ((float4*)out)[node * 16 + lane * 2 + 1] = o1;
}

extern "C" void kernel_launch(void* const* d_in, const int* in_sizes, int n_in,
                              void* d_out, int out_size)
{
    const float* x  = (const float*)d_in[0];
    const int*   ei = (const int*)d_in[1];
    const float* w  = (const float*)d_in[2];
    const float* b  = (const float*)d_in[3];
    float*       out = (float*)d_out;
    (void)in_sizes; (void)n_in; (void)out_size;

    // one-time host objects (not device memory)
    static cudaStream_t s2 = nullptr;
    static cudaEvent_t evA = nullptr, evB = nullptr;
    if (!s2) {
        cudaStreamCreateWithFlags(&s2, cudaStreamNonBlocking);
        cudaEventCreateWithFlags(&evA, cudaEventDisableTiming);
        cudaEventCreateWithFlags(&evB, cudaEventDisableTiming);
    }

    // fork at the very top: gemm depends only on x, w
    cudaEventRecord(evA, 0);
    cudaStreamWaitEvent(s2, evA, 0);
    k_gemm<<<(N_NODES + 63) / 64, 128, 0, s2>>>(x, w);
    cudaEventRecord(evB, s2);

    // edge pipeline on the capture stream
    k_zero <<<NBLK, 256>>>();
    k_count<<<(N_EDGES + 255) / 256, 256>>>(ei);
    k_scanF<<<NBLK, 256>>>();
    k_place<<<(N_EDGES + 255) / 256, 256>>>(ei);

    // join: gather needs both place (stream 0) and gemm (s2)
    cudaStreamWaitEvent(0, evB, 0);
    long long total_threads = (long long)N_NODES * 8;
    int blocks = (int)((total_threads + 255) / 256);
    k_gather<<<blocks, 256>>>(b, out);
}

// round 9
// speedup vs baseline: 1.0847x; 1.0847x over previous
#include <cuda_runtime.h>
#include <cuda_fp16.h>

#define N_NODES 100000
#define N_EDGES 1250000
#define F 64
#define NBLK 391        // ceil(N_NODES/256)

// Scratch (device globals — no allocation allowed in kernel_launch)
__device__ int   g_deg[N_NODES];
__device__ float g_dinv[N_NODES];
__device__ int   g_row_start[N_NODES + 1];
__device__ int   g_cursor[N_NODES];
__device__ unsigned long long g_bsv[512];            // flagged block sums
__device__ int   g_ssrc[N_EDGES];                    // src ids sorted by dst
__device__ __align__(16) __half g_hs[N_NODES * F];   // fp16 hs (dinv-scaled)

__global__ void k_zero() {
    int i = blockIdx.x * blockDim.x + threadIdx.x;
    if (i < N_NODES) g_deg[i] = 0;
    if (i < 512) g_bsv[i] = 0ULL;
}

__global__ void k_count(const int* __restrict__ ei) {
    int e = blockIdx.x * blockDim.x + threadIdx.x;
    if (e < N_EDGES) atomicAdd(&g_deg[ei[N_EDGES + e]], 1);
}

// Single-pass exclusive scan over g_deg (publish block total, poll predecessors)
// + dinv + cursor init, all fused.
__global__ void k_scanF() {
    __shared__ int sd[256];
    const int tid = threadIdx.x, bid = blockIdx.x;
    const int i = bid * 256 + tid;
    int v = (i < N_NODES) ? g_deg[i] : 0;
    sd[tid] = v;
    __syncthreads();
    #pragma unroll
    for (int off = 1; off < 256; off <<= 1) {
        int t = (tid >= off) ? sd[tid - off] : 0;
        __syncthreads();
        sd[tid] += t;
        __syncthreads();
    }
    int incl = sd[tid];
    // publish own block total BEFORE polling predecessors (no circular wait)
    if (tid == 255)
        atomicExch(&g_bsv[bid], (1ULL << 63) | (unsigned long long)(unsigned)incl);

    // poll predecessors: thread t handles p = t, t+256 (< bid)
    int s = 0;
    for (int p = tid; p < bid; p += 256) {
        unsigned long long x;
        do { x = atomicAdd(&g_bsv[p], 0ULL); } while (!(x >> 63));
        s += (int)(unsigned)x;
    }
    __syncthreads();
    sd[tid] = s;
    __syncthreads();
    #pragma unroll
    for (int off = 128; off > 0; off >>= 1) {
        if (tid < off) sd[tid] += sd[tid + off];
        __syncthreads();
    }
    int boff = sd[0];

    if (i < N_NODES) {
        int rs = incl - v + boff;            // exclusive global offset
        g_row_start[i] = rs;
        g_cursor[i] = rs;
        g_dinv[i] = rsqrtf((float)v + 1.0f); // +1 self-loop
    }
    if (i == 0) g_row_start[N_NODES] = N_EDGES;
}

__global__ void k_place(const int* __restrict__ ei) {
    int e = blockIdx.x * blockDim.x + threadIdx.x;
    if (e < N_EDGES) {
        int d = ei[N_EDGES + e];
        int pos = atomicAdd(&g_cursor[d], 1);
        g_ssrc[pos] = ei[e];
    }
}

// ---- tensor-core GEMM: hs[n][j] = (x[n] . W[j]) * dinv[n], fp16 out ----
__device__ __forceinline__ unsigned pack_h2(float lo, float hi) {
    __half2 h = __floats2half2_rn(lo, hi);   // lo -> low half
    return *reinterpret_cast<unsigned*>(&h);
}

__device__ __forceinline__ void mma16816(float* c,
    unsigned a0, unsigned a1, unsigned a2, unsigned a3,
    unsigned b0, unsigned b1)
{
    asm volatile(
        "mma.sync.aligned.m16n8k16.row.col.f32.f16.f16.f32 "
        "{%0,%1,%2,%3}, {%4,%5,%6,%7}, {%8,%9}, {%0,%1,%2,%3};"
        : "+f"(c[0]), "+f"(c[1]), "+f"(c[2]), "+f"(c[3])
        : "r"(a0), "r"(a1), "r"(a2), "r"(a3), "r"(b0), "r"(b1));
}

// 256 threads, 128 rows/block. x staged through smem as fp16 (coalesced
// LDG.128, conflict-free STS/LDS: bank = 4g+t = lane, distinct).
#define XH_STRIDE 72
#define WH_STRIDE 72
__global__ void __launch_bounds__(256) k_gemm(
    const float* __restrict__ x, const float* __restrict__ w)
{
    __shared__ __half Wh[64 * WH_STRIDE];    // [j][k] halves
    __shared__ __half Xh[128 * XH_STRIDE];   // [r][k] halves
    const int tid = threadIdx.x;
    const int n_base = blockIdx.x * 128;

    {   // Stage W: 1024 float4, 4 per thread
        const float4* w4 = (const float4*)w;
        #pragma unroll
        for (int r = 0; r < 4; r++) {
            int idx = tid + 256 * r;        // 0..1023
            int j  = idx >> 4;
            int kq = idx & 15;              // k/4
            float4 v = w4[idx];
            *reinterpret_cast<unsigned*>(&Wh[j * WH_STRIDE + kq * 4])     = pack_h2(v.x, v.y);
            *reinterpret_cast<unsigned*>(&Wh[j * WH_STRIDE + kq * 4 + 2]) = pack_h2(v.z, v.w);
        }
    }
    {   // Stage X: 128 rows x 16 float4 = 2048 float4, 8 per thread (independent LDGs)
        const float4* x4 = (const float4*)x;
        float4 v[8];
        #pragma unroll
        for (int r = 0; r < 8; r++) {
            int idx = tid + 256 * r;        // 0..2047
            int row = n_base + (idx >> 4);
            v[r] = (row < N_NODES) ? x4[(size_t)row * 16 + (idx & 15)]
                                   : make_float4(0.f, 0.f, 0.f, 0.f);
        }
        #pragma unroll
        for (int r = 0; r < 8; r++) {
            int idx = tid + 256 * r;
            int row = idx >> 4;
            int kq  = idx & 15;
            *reinterpret_cast<unsigned*>(&Xh[row * XH_STRIDE + kq * 4])     = pack_h2(v[r].x, v[r].y);
            *reinterpret_cast<unsigned*>(&Xh[row * XH_STRIDE + kq * 4 + 2]) = pack_h2(v[r].z, v[r].w);
        }
    }
    __syncthreads();

    const int warp = tid >> 5, lane = tid & 31;
    const int g = lane >> 2, t = lane & 3;
    const int lr0 = warp * 16 + g;                 // local rows lr0, lr0+8
    const int r0 = n_base + lr0;
    const int r1 = r0 + 8;
    const bool v0 = r0 < N_NODES, v1 = r1 < N_NODES;

    float acc[8][4] = {};   // 8 n-tiles x (c0..c3)

    #pragma unroll
    for (int kc = 0; kc < 4; kc++) {
        const int kk = kc * 16 + t * 2;
        unsigned a0 = *reinterpret_cast<const unsigned*>(&Xh[lr0 * XH_STRIDE + kk]);
        unsigned a1 = *reinterpret_cast<const unsigned*>(&Xh[(lr0 + 8) * XH_STRIDE + kk]);
        unsigned a2 = *reinterpret_cast<const unsigned*>(&Xh[lr0 * XH_STRIDE + kk + 8]);
        unsigned a3 = *reinterpret_cast<const unsigned*>(&Xh[(lr0 + 8) * XH_STRIDE + kk + 8]);

        #pragma unroll
        for (int nt = 0; nt < 8; nt++) {
            int n = nt * 8 + g;            // B col (output feature j)
            unsigned b0 = *reinterpret_cast<const unsigned*>(&Wh[n * WH_STRIDE + kk]);
            unsigned b1 = *reinterpret_cast<const unsigned*>(&Wh[n * WH_STRIDE + kk + 8]);
            mma16816(acc[nt], a0, a1, a2, a3, b0, b1);
        }
    }

    // Epilogue: scale by dinv, store fp16
    float dv0 = v0 ? g_dinv[r0] : 0.f;
    float dv1 = v1 ? g_dinv[r1] : 0.f;
    #pragma unroll
    for (int nt = 0; nt < 8; nt++) {
        int col = nt * 8 + t * 2;          // D cols col, col+1
        if (v0)
            *reinterpret_cast<unsigned*>(&g_hs[(size_t)r0 * F + col]) =
                pack_h2(acc[nt][0] * dv0, acc[nt][1] * dv0);
        if (v1)
            *reinterpret_cast<unsigned*>(&g_hs[(size_t)r1 * F + col]) =
                pack_h2(acc[nt][2] * dv1, acc[nt][3] * dv1);
    }
}

__device__ __forceinline__ void acc8(float* a, uint4 v) {
    const __half2* h = reinterpret_cast<const __half2*>(&v);
    #pragma unroll
    for (int q = 0; q < 4; q++) {
        float2 f = __half22float2(h[q]);
        a[2 * q]     += f.x;
        a[2 * q + 1] += f.y;
    }
}

// CSR gather: 8 lanes per node; one LDG.128 (8 halves) per edge per lane.
__global__ void __launch_bounds__(256) k_gather(
    const float* __restrict__ bias, float* __restrict__ out)
{
    long long tt = blockIdx.x * (long long)blockDim.x + threadIdx.x;
    int node = (int)(tt >> 3);
    int lane = threadIdx.x & 7;
    if (node >= N_NODES) return;

    const uint4* hs16 = (const uint4*)g_hs;   // 8 uint4 per row
    float a[8] = {0.f, 0.f, 0.f, 0.f, 0.f, 0.f, 0.f, 0.f};
    acc8(a, hs16[node * 8 + lane]);           // self-loop term

    int e   = __ldg(&g_row_start[node]);
    int end = __ldg(&g_row_start[node + 1]);

    for (; e + 2 <= end; e += 2) {
        int s0 = __ldg(&g_ssrc[e]);
        int s1 = __ldg(&g_ssrc[e + 1]);
        uint4 u0 = hs16[s0 * 8 + lane];
        uint4 u1 = hs16[s1 * 8 + lane];
        acc8(a, u0);
        acc8(a, u1);
    }
    if (e < end) {
        int s0 = __ldg(&g_ssrc[e]);
        acc8(a, hs16[s0 * 8 + lane]);
    }

    float dv = __ldg(&g_dinv[node]);
    const float4* b4 = (const float4*)bias;
    float4 ba = b4[lane * 2], bb = b4[lane * 2 + 1];
    float4 o0, o1;
    o0.x = ba.x + dv * a[0]; o0.y = ba.y + dv * a[1];
    o0.z = ba.z + dv * a[2]; o0.w = ba.w + dv * a[3];
    o1.x = bb.x + dv * a[4]; o1.y = bb.y + dv * a[5];
    o1.z = bb.z + dv * a[6]; o1.w = bb.w + dv * a[7];
    ((float4*)out)[node * 16 + lane * 2]     = o0;
    ((float4*)out)[node * 16 + lane * 2 + 1] = o1;
}

extern "C" void kernel_launch(void* const* d_in, const int* in_sizes, int n_in,
                              void* d_out, int out_size)
{
    const float* x  = (const float*)d_in[0];
    const int*   ei = (const int*)d_in[1];
    const float* w  = (const float*)d_in[2];
    const float* b  = (const float*)d_in[3];
    float*       out = (float*)d_out;
    (void)in_sizes; (void)n_in; (void)out_size;

    // one-time host objects (not device memory)
    static cudaStream_t s2 = nullptr;
    static cudaEvent_t evA = nullptr, evB = nullptr;
    if (!s2) {
        cudaStreamCreateWithFlags(&s2, cudaStreamNonBlocking);
        cudaEventCreateWithFlags(&evA, cudaEventDisableTiming);
        cudaEventCreateWithFlags(&evB, cudaEventDisableTiming);
    }

    k_zero <<<NBLK, 256>>>();
    k_count<<<(N_EDGES + 255) / 256, 256>>>(ei);
    k_scanF<<<NBLK, 256>>>();

    // fork: gemm (needs dinv from scanF) runs concurrent with place
    cudaEventRecord(evA, 0);
    cudaStreamWaitEvent(s2, evA, 0);
    k_gemm<<<(N_NODES + 127) / 128, 256, 0, s2>>>(x, w);
    cudaEventRecord(evB, s2);

    k_place<<<(N_EDGES + 255) / 256, 256>>>(ei);

    // join: gather needs both place (stream 0) and gemm (s2)
    cudaStreamWaitEvent(0, evB, 0);
    long long total_threads = (long long)N_NODES * 8;
    int blocks = (int)((total_threads + 255) / 256);
    k_gather<<<blocks, 256>>>(b, out);
}